// round 13
// baseline (speedup 1.0000x reference)
#include <cuda_runtime.h>
#include <float.h>

// Problem constants
#define NB     8
#define NC1    2048
#define HW     56
#define PLANE  (HW*HW)          // 3136
#define SR     60               // smem row stride (floats)
#define SPLANE (58*SR + 4)      // 3484 floats: pad so SPLANE%32=28 (ic bank spread)
#define NPLANES 16
#define SMEM_BYTES (NPLANES*SPLANE*4)   // 222976 B
#define OC_PER_BLK 128
#define NTHREADS 512
#define NTASKS 3584             // 2 halves * 128 oc * 14 sx = 512 * 7 exactly

// 0 = index stored as int32 (JAX default, x64 disabled), 1 = genuine int64
__device__ int g_idx_is_i64;

__global__ void detect_index_dtype(const unsigned int* __restrict__ idx_words) {
    // int64 layout: odd words (high halves) of first 32 entries are all 0.
    // int32 layout: those words are index[1],[3],...,[63] of a permutation of
    // [0,8192): at most one of them is zero.
    if (threadIdx.x == 0) {
        int any_nonzero = 0;
        for (int k = 0; k < 32; k++) any_nonzero |= (idx_words[2*k + 1] != 0u);
        g_idx_is_i64 = !any_nonzero;
    }
}

__global__ __launch_bounds__(NTHREADS)
void fused_conv_gather_max(const float* __restrict__ x,
                           const float* __restrict__ Wt,
                           const float* __restrict__ b1,
                           const int* __restrict__ index32,
                           float* __restrict__ out) {
    extern __shared__ float sm[];   // 16 padded planes
    const int ocg = blockIdx.x;     // oc group (0..15)
    const int n   = blockIdx.y;
    const int tid = threadIdx.x;
    const int is64 = g_idx_is_i64;

    // ---- Stage all 16 input planes once (aligned STS.128 via shuffle) ----
    // Padded: plane[r+1][c+1] = x[r][c]; float4 group hl of a padded row is
    // {in[4hl-1], in[4hl], in[4hl+1], in[4hl+2]}.
    const int grp = tid >> 4;       // 0..31 (16-lane groups)
    const int hl  = tid & 15;
#pragma unroll 1
    for (int g = 0; g < NPLANES; g++) {
        const float* src = x + (long)(n*NPLANES + g)*PLANE;
        float* pb = sm + g*SPLANE;
#pragma unroll 1
        for (int r = grp; r < HW; r += 32) {
            float4 v = make_float4(0.f, 0.f, 0.f, 0.f);
            if (hl < 14) v = ((const float4*)(src + r*HW))[hl];
            float pw = __shfl_up_sync(0xffffffffu, v.w, 1, 16);
            float4 o = make_float4(hl ? pw : 0.f, v.x, v.y, v.z);
            if (hl < 15) ((float4*)(pb + (r+1)*SR))[hl] = o;   // aligned STS.128
        }
    }
    // Zero padded bottom row 57 of each plane (row 0 is never read: the
    // partial-sum init below accounts for it). 16 planes x 15 float4.
    if (tid < NPLANES*15) {
        int g = tid / 15, q = tid - g*15;
        ((float4*)(sm + g*SPLANE + 57*SR))[q] = make_float4(0.f, 0.f, 0.f, 0.f);
    }
    __syncthreads();

    // ---- Tasks: 7 per thread, half-major: t = half*1792 + ocl*14 + sx ----
    // A warp's lanes share one half (kills the +20-bank half collision);
    // consecutive lanes are consecutive sx within an ocl.
#pragma unroll 1
    for (int p = 0; p < 7; p++) {
        const int t    = p*NTHREADS + tid;
        const int half = t / 1792;
        const int s    = t - half*1792;
        const int ocl  = s / 14;
        const int sx   = s - ocl*14;
        const int oc   = ocg*OC_PER_BLK + ocl;

        // Resolve 4 source channels; load weights/bias
        float k[4][9], bs[4];
        const float* rp[4];
#pragma unroll
        for (int g = 0; g < 4; g++) {
            int iv;
            if (is64) iv = (int)((const long long*)index32)[oc*4 + g];
            else      iv = index32[oc*4 + g];
            int c  = iv & (NC1 - 1);
            int ic = c >> 7;                 // 128 out-channels per input chan
            // First padded row this task touches: 1 for half 0, 28 for half 1
            rp[g] = sm + ic*SPLANE + sx*4 + (half ? 28*SR : SR);
            const float* wp = Wt + c*9;
#pragma unroll
            for (int j = 0; j < 9; j++) k[g][j] = __ldg(wp + j);
            bs[g] = __ldg(b1 + c);
        }

        // Partial-row accumulators per channel:
        //  p1[g][j] = bias + top-taps of the next output row
        //  p0[g][j] = p1 + mid-taps (completed by bot-taps of current scan row)
        float p0[4][4], p1[4][4];

        // Peel A (half 1 only): p1 = bias + top-taps of padded row 28
        if (half) {
#pragma unroll
            for (int g = 0; g < 4; g++) {
                float4 a = *(const float4*)rp[g];
                float2 bq = *(const float2*)(rp[g] + 4);
                rp[g] += SR;
                float v0=a.x, v1=a.y, v2=a.z, v3=a.w, v4=bq.x, v5=bq.y;
#pragma unroll
                for (int j = 0; j < 4; j++) {
                    float w0 = (j==0)?v0:(j==1)?v1:(j==2)?v2:v3;
                    float w1 = (j==0)?v1:(j==1)?v2:(j==2)?v3:v4;
                    float w2 = (j==0)?v2:(j==1)?v3:(j==2)?v4:v5;
                    p1[g][j] = fmaf(k[g][2], w2, fmaf(k[g][1], w1, fmaf(k[g][0], w0, bs[g])));
                }
            }
        } else {
#pragma unroll
            for (int g = 0; g < 4; g++)
#pragma unroll
                for (int j = 0; j < 4; j++) p1[g][j] = bs[g];  // zero top row
        }

        // Peel B: p0 = p1 + mid-taps; p1 = bias + top-taps (padded row 1 or 29)
#pragma unroll
        for (int g = 0; g < 4; g++) {
            float4 a = *(const float4*)rp[g];
            float2 bq = *(const float2*)(rp[g] + 4);
            rp[g] += SR;
            float v0=a.x, v1=a.y, v2=a.z, v3=a.w, v4=bq.x, v5=bq.y;
#pragma unroll
            for (int j = 0; j < 4; j++) {
                float w0 = (j==0)?v0:(j==1)?v1:(j==2)?v2:v3;
                float w1 = (j==0)?v1:(j==1)?v2:(j==2)?v3:v4;
                float w2 = (j==0)?v2:(j==1)?v3:(j==2)?v4:v5;
                p0[g][j] = fmaf(k[g][5], w2, fmaf(k[g][4], w1, fmaf(k[g][3], w0, p1[g][j])));
                p1[g][j] = fmaf(k[g][2], w2, fmaf(k[g][1], w1, fmaf(k[g][0], w0, bs[g])));
            }
        }

        float* outp = out + ((long)(n*NC1 + oc))*PLANE + (half*28)*HW + sx*4;

        // 28 output rows. All 8 LDS issued up-front each iteration (MLP=8),
        // then the 144 FMAs, then a pairwise max tree.
#pragma unroll 2
        for (int rr = 0; rr < 28; rr++) {
            float4 a_[4]; float2 q_[4];
#pragma unroll
            for (int g = 0; g < 4; g++) {
                a_[g] = *(const float4*)rp[g];
                q_[g] = *(const float2*)(rp[g] + 4);
                rp[g] += SR;
            }
            float cr[4][4];
#pragma unroll
            for (int g = 0; g < 4; g++) {
                float v0=a_[g].x, v1=a_[g].y, v2=a_[g].z, v3=a_[g].w;
                float v4=q_[g].x, v5=q_[g].y;
                const float k0=k[g][0], k1=k[g][1], k2=k[g][2];
                const float k3=k[g][3], k4=k[g][4], k5=k[g][5];
                const float k6=k[g][6], k7=k[g][7], k8=k[g][8];
                const float bb = bs[g];
#pragma unroll
                for (int j = 0; j < 4; j++) {
                    float w0 = (j==0)?v0:(j==1)?v1:(j==2)?v2:v3;
                    float w1 = (j==0)?v1:(j==1)?v2:(j==2)?v3:v4;
                    float w2 = (j==0)?v2:(j==1)?v3:(j==2)?v4:v5;
                    cr[g][j] = fmaf(k8, w2, fmaf(k7, w1, fmaf(k6, w0, p0[g][j])));
                    p0[g][j] = fmaf(k5, w2, fmaf(k4, w1, fmaf(k3, w0, p1[g][j])));
                    p1[g][j] = fmaf(k2, w2, fmaf(k1, w1, fmaf(k0, w0, bb)));
                }
            }
            float m0 = fmaxf(fmaxf(cr[0][0], cr[1][0]), fmaxf(cr[2][0], cr[3][0]));
            float m1 = fmaxf(fmaxf(cr[0][1], cr[1][1]), fmaxf(cr[2][1], cr[3][1]));
            float m2 = fmaxf(fmaxf(cr[0][2], cr[1][2]), fmaxf(cr[2][2], cr[3][2]));
            float m3 = fmaxf(fmaxf(cr[0][3], cr[1][3]), fmaxf(cr[2][3], cr[3][3]));
            *(float4*)outp = make_float4(m0, m1, m2, m3);
            outp += HW;
        }
    }
}

extern "C" void kernel_launch(void* const* d_in, const int* in_sizes, int n_in,
                              void* d_out, int out_size) {
    const float* x     = (const float*)d_in[0];
    const float* Wt    = (const float*)d_in[1];
    const float* b1    = (const float*)d_in[2];
    const int*   index = (const int*)d_in[3];
    float*       out   = (float*)d_out;

    cudaFuncSetAttribute(fused_conv_gather_max,
                         cudaFuncAttributeMaxDynamicSharedMemorySize, SMEM_BYTES);

    detect_index_dtype<<<1, 32>>>((const unsigned int*)index);

    dim3 grid(NC1/OC_PER_BLK, NB);   // 16 x 8 = 128 blocks
    fused_conv_gather_max<<<grid, NTHREADS, SMEM_BYTES>>>(x, Wt, b1, index, out);
}

// round 14
// speedup vs baseline: 1.0799x; 1.0799x over previous
#include <cuda_runtime.h>
#include <float.h>

// Problem constants
#define NB     8
#define NC1    2048
#define HW     56
#define PLANE  (HW*HW)          // 3136
#define SR     60               // smem row stride (floats)
#define SPLANE (58*SR + 4)      // 3484: ic base-bank spread uniform (28=4*7)
#define NPLANES 16
#define SMEM_BYTES (NPLANES*SPLANE*4)   // 222976 B
#define OC_PER_BLK 128
#define NTHREADS 512
#define NTASKS 3584             // 128 oc * 14 sx * 2 halves = 512 * 7 exactly

// 0 = index stored as int32 (JAX default, x64 disabled), 1 = genuine int64
__device__ int g_idx_is_i64;

__global__ void detect_index_dtype(const unsigned int* __restrict__ idx_words) {
    // int64 layout: odd words (high halves) of first 32 entries are all 0.
    // int32 layout: those words are index[1],[3],...,[63] of a permutation of
    // [0,8192): at most one of them is zero.
    if (threadIdx.x == 0) {
        int any_nonzero = 0;
        for (int k = 0; k < 32; k++) any_nonzero |= (idx_words[2*k + 1] != 0u);
        g_idx_is_i64 = !any_nonzero;
    }
}

__global__ __launch_bounds__(NTHREADS)
void fused_conv_gather_max(const float* __restrict__ x,
                           const float* __restrict__ Wt,
                           const float* __restrict__ b1,
                           const int* __restrict__ index32,
                           float* __restrict__ out) {
    extern __shared__ float sm[];   // 16 padded planes
    const int ocg = blockIdx.x;     // oc group (0..15)
    const int n   = blockIdx.y;
    const int tid = threadIdx.x;
    const int is64 = g_idx_is_i64;

    // ---- Stage all 16 input planes once (aligned STS.128 via shuffle) ----
    // Padded: plane[r+1][c+1] = x[r][c]; float4 group hl of a padded row is
    // {in[4hl-1], in[4hl], in[4hl+1], in[4hl+2]}.
    const int grp = tid >> 4;       // 0..31 (16-lane groups)
    const int hl  = tid & 15;
#pragma unroll 1
    for (int g = 0; g < NPLANES; g++) {
        const float* src = x + (long)(n*NPLANES + g)*PLANE;
        float* pb = sm + g*SPLANE;
#pragma unroll 1
        for (int r = grp; r < HW; r += 32) {
            float4 v = make_float4(0.f, 0.f, 0.f, 0.f);
            if (hl < 14) v = ((const float4*)(src + r*HW))[hl];
            float pw = __shfl_up_sync(0xffffffffu, v.w, 1, 16);
            float4 o = make_float4(hl ? pw : 0.f, v.x, v.y, v.z);
            if (hl < 15) ((float4*)(pb + (r+1)*SR))[hl] = o;   // aligned STS.128
        }
    }
    // Zero padded bottom row 57 of each plane (row 0 is never read: the
    // partial-sum init below accounts for it). 16 planes x 15 float4.
    if (tid < NPLANES*15) {
        int g = tid / 15, q = tid - g*15;
        ((float4*)(sm + g*SPLANE + 57*SR))[q] = make_float4(0.f, 0.f, 0.f, 0.f);
    }
    __syncthreads();

    // ---- Tasks: 7 per thread, each = (ocl, sx, half) covering 28 rows ----
    // (R12 map: lane pairs share (ocl,sx), halves interleaved.)
#pragma unroll 1
    for (int p = 0; p < 7; p++) {
        const int t    = p*NTHREADS + tid;
        const int ocl  = t / 28;
        const int rem  = t - ocl*28;
        const int sx   = rem >> 1;
        const int half = rem & 1;
        const int oc   = ocg*OC_PER_BLK + ocl;

        // Resolve 4 source channels; load weights/bias
        float k[4][9], bs[4];
        const float* rp[4];
#pragma unroll
        for (int g = 0; g < 4; g++) {
            int iv;
            if (is64) iv = (int)((const long long*)index32)[oc*4 + g];
            else      iv = index32[oc*4 + g];
            int c  = iv & (NC1 - 1);
            int ic = c >> 7;                 // 128 out-channels per input chan
            // First padded row this task touches: 1 for half 0, 28 for half 1
            rp[g] = sm + ic*SPLANE + sx*4 + (half ? 28*SR : SR);
            const float* wp = Wt + c*9;
#pragma unroll
            for (int j = 0; j < 9; j++) k[g][j] = __ldg(wp + j);
            bs[g] = __ldg(b1 + c);
        }

        // Partial-row accumulators per channel:
        //  p1[g][j] = bias + top-taps of the next output row
        //  p0[g][j] = p1 + mid-taps (completed by bot-taps of current scan row)
        float p0[4][4], p1[4][4];

        // Peel A (half 1 only): p1 = bias + top-taps of padded row 28
        if (half) {
#pragma unroll
            for (int g = 0; g < 4; g++) {
                float4 a = *(const float4*)rp[g];
                float2 bq = *(const float2*)(rp[g] + 4);
                rp[g] += SR;
                float v0=a.x, v1=a.y, v2=a.z, v3=a.w, v4=bq.x, v5=bq.y;
#pragma unroll
                for (int j = 0; j < 4; j++) {
                    float w0 = (j==0)?v0:(j==1)?v1:(j==2)?v2:v3;
                    float w1 = (j==0)?v1:(j==1)?v2:(j==2)?v3:v4;
                    float w2 = (j==0)?v2:(j==1)?v3:(j==2)?v4:v5;
                    p1[g][j] = fmaf(k[g][2], w2, fmaf(k[g][1], w1, fmaf(k[g][0], w0, bs[g])));
                }
            }
        } else {
#pragma unroll
            for (int g = 0; g < 4; g++)
#pragma unroll
                for (int j = 0; j < 4; j++) p1[g][j] = bs[g];  // zero top row
        }

        // Peel B: p0 = p1 + mid-taps; p1 = bias + top-taps (padded row 1 or 29)
#pragma unroll
        for (int g = 0; g < 4; g++) {
            float4 a = *(const float4*)rp[g];
            float2 bq = *(const float2*)(rp[g] + 4);
            rp[g] += SR;
            float v0=a.x, v1=a.y, v2=a.z, v3=a.w, v4=bq.x, v5=bq.y;
#pragma unroll
            for (int j = 0; j < 4; j++) {
                float w0 = (j==0)?v0:(j==1)?v1:(j==2)?v2:v3;
                float w1 = (j==0)?v1:(j==1)?v2:(j==2)?v3:v4;
                float w2 = (j==0)?v2:(j==1)?v3:(j==2)?v4:v5;
                p0[g][j] = fmaf(k[g][5], w2, fmaf(k[g][4], w1, fmaf(k[g][3], w0, p1[g][j])));
                p1[g][j] = fmaf(k[g][2], w2, fmaf(k[g][1], w1, fmaf(k[g][0], w0, bs[g])));
            }
        }

        float* outp = out + ((long)(n*NC1 + oc))*PLANE + (half*28)*HW + sx*4;

        // 28 output rows. All 8 LDS issued up-front each iteration (MLP=8);
        // unroll 4 widens the scheduling window across rows.
#pragma unroll 4
        for (int rr = 0; rr < 28; rr++) {
            float4 a_[4]; float2 q_[4];
#pragma unroll
            for (int g = 0; g < 4; g++) {
                a_[g] = *(const float4*)rp[g];
                q_[g] = *(const float2*)(rp[g] + 4);
                rp[g] += SR;
            }
            float cr[4][4];
#pragma unroll
            for (int g = 0; g < 4; g++) {
                float v0=a_[g].x, v1=a_[g].y, v2=a_[g].z, v3=a_[g].w;
                float v4=q_[g].x, v5=q_[g].y;
                const float k0=k[g][0], k1=k[g][1], k2=k[g][2];
                const float k3=k[g][3], k4=k[g][4], k5=k[g][5];
                const float k6=k[g][6], k7=k[g][7], k8=k[g][8];
                const float bb = bs[g];
#pragma unroll
                for (int j = 0; j < 4; j++) {
                    float w0 = (j==0)?v0:(j==1)?v1:(j==2)?v2:v3;
                    float w1 = (j==0)?v1:(j==1)?v2:(j==2)?v3:v4;
                    float w2 = (j==0)?v2:(j==1)?v3:(j==2)?v4:v5;
                    cr[g][j] = fmaf(k8, w2, fmaf(k7, w1, fmaf(k6, w0, p0[g][j])));
                    p0[g][j] = fmaf(k5, w2, fmaf(k4, w1, fmaf(k3, w0, p1[g][j])));
                    p1[g][j] = fmaf(k2, w2, fmaf(k1, w1, fmaf(k0, w0, bb)));
                }
            }
            float m0 = fmaxf(fmaxf(cr[0][0], cr[1][0]), fmaxf(cr[2][0], cr[3][0]));
            float m1 = fmaxf(fmaxf(cr[0][1], cr[1][1]), fmaxf(cr[2][1], cr[3][1]));
            float m2 = fmaxf(fmaxf(cr[0][2], cr[1][2]), fmaxf(cr[2][2], cr[3][2]));
            float m3 = fmaxf(fmaxf(cr[0][3], cr[1][3]), fmaxf(cr[2][3], cr[3][3]));
            *(float4*)outp = make_float4(m0, m1, m2, m3);
            outp += HW;
        }
    }
}

extern "C" void kernel_launch(void* const* d_in, const int* in_sizes, int n_in,
                              void* d_out, int out_size) {
    const float* x     = (const float*)d_in[0];
    const float* Wt    = (const float*)d_in[1];
    const float* b1    = (const float*)d_in[2];
    const int*   index = (const int*)d_in[3];
    float*       out   = (float*)d_out;

    cudaFuncSetAttribute(fused_conv_gather_max,
                         cudaFuncAttributeMaxDynamicSharedMemorySize, SMEM_BYTES);

    detect_index_dtype<<<1, 32>>>((const unsigned int*)index);

    dim3 grid(NC1/OC_PER_BLK, NB);   // 16 x 8 = 128 blocks
    fused_conv_gather_max<<<grid, NTHREADS, SMEM_BYTES>>>(x, Wt, b1, index, out);
}